// round 9
// baseline (speedup 1.0000x reference)
#include <cuda_runtime.h>
#include <cuda.h>
#include <cuda_fp16.h>

#define NN 50000
#define NE 800000
#define H  128
#define SCAN_B 1024
#define NBLK ((NN + SCAN_B - 1) / SCAN_B)   // 49

// Scratch (device globals; no allocation allowed)
__device__ float   g_inv[NN];
__device__ int     g_cnt[NN];               // zero at entry (static init + scan resets)
__device__ int     g_off[NN + 1];
__device__ int     g_pos[NN];
__device__ int     g_flag[NBLK];            // lookback status: 0 inv, 1 agg, 2 prefix
__device__ int     g_aggv[NBLK];
__device__ int     g_pref[NBLK];
__device__ int2    g_epair[NE];             // {src, edge_id} bucketed by dst
__device__ __align__(16) __half2 g_mx[NN * 64];   // x0 mirror; later final features
__device__ __align__(16) __half2 g_mh[NN * 64];   // layer-1 output
__device__ __align__(16) __half  g_w1[H * 2 * H]; // [o][k] concat: k<128 Wl, k>=128 Wr
__device__ __align__(16) __half  g_w2[H * 2 * H];

// ---------------------------------------------------------------------------
// prep: gather x0 mirror, convert both weight mats
// ---------------------------------------------------------------------------
__global__ __launch_bounds__(256) void k_prep(const float* __restrict__ emb,
                                              const int* __restrict__ nid,
                                              const float* __restrict__ Wl1,
                                              const float* __restrict__ Wr1,
                                              const float* __restrict__ Wl2,
                                              const float* __restrict__ Wr2) {
    int i = blockIdx.x * blockDim.x + threadIdx.x;   // half2 index
    if (i < NN * 64) {
        int r = i >> 6;
        int n = nid[r];
        float2 v = ((const float2*)(emb + (size_t)n * H))[i & 63];
        g_mx[i] = __floats2half2_rn(v.x, v.y);
    }
    if (i < H * 2 * H) {
        int o = i >> 8, k = i & 255;
        g_w1[i] = __float2half((k < H) ? Wl1[o * H + k] : Wr1[o * H + (k - H)]);
        g_w2[i] = __float2half((k < H) ? Wl2[o * H + k] : Wr2[o * H + (k - H)]);
    }
}

// count edges per dst (g_cnt is zero at entry); also reset lookback flags
__global__ __launch_bounds__(256) void k_count(const int* __restrict__ dst) {
    int e = blockIdx.x * blockDim.x + threadIdx.x;
    if (e < NBLK) g_flag[e] = 0;
    if (e < NE) atomicAdd(&g_cnt[dst[e]], 1);
}

// ---------------------------------------------------------------------------
// single-pass decoupled-lookback scan: g_cnt -> g_off/g_pos/g_inv; resets g_cnt
// (49 blocks <= #SMs, all co-resident -> lookback is deadlock-free)
// ---------------------------------------------------------------------------
__global__ __launch_bounds__(SCAN_B) void k_scan() {
    __shared__ int warp_sums[32];
    __shared__ int s_excl;
    int tid = threadIdx.x;
    int lane = tid & 31, w = tid >> 5;
    int b = blockIdx.x;
    int i = b * SCAN_B + tid;
    int v = (i < NN) ? g_cnt[i] : 0;
    int xs = v;
#pragma unroll
    for (int off = 1; off < 32; off <<= 1) {
        int t = __shfl_up_sync(0xFFFFFFFFu, xs, off);
        if (lane >= off) xs += t;
    }
    if (lane == 31) warp_sums[w] = xs;
    __syncthreads();
    if (w == 0) {
        int s = warp_sums[lane];
#pragma unroll
        for (int off = 1; off < 32; off <<= 1) {
            int t = __shfl_up_sync(0xFFFFFFFFu, s, off);
            if (lane >= off) s += t;
        }
        warp_sums[lane] = s;
    }
    __syncthreads();
    int incl = xs + (w > 0 ? warp_sums[w - 1] : 0);
    int total = warp_sums[31];

    if (tid == 0) {
        volatile int* vflag = g_flag;
        volatile int* vaggv = g_aggv;
        volatile int* vpref = g_pref;
        if (b == 0) {
            vpref[0] = total;
            __threadfence();
            vflag[0] = 2;
            s_excl = 0;
        } else {
            vaggv[b] = total;
            __threadfence();
            vflag[b] = 1;
            int excl = 0;
            for (int j = b - 1; j >= 0;) {
                int f;
                do { f = vflag[j]; } while (f == 0);
                if (f == 2) { excl += vpref[j]; break; }
                excl += vaggv[j];
                j--;
            }
            vpref[b] = excl + total;
            __threadfence();
            vflag[b] = 2;
            s_excl = excl;
        }
    }
    __syncthreads();
    if (i < NN) {
        int e = incl - v + s_excl;
        g_off[i] = e;
        g_pos[i] = e;
        g_inv[i] = 1.0f / (float)max(v, 1);
        g_cnt[i] = 0;            // restore invariant for next call
    }
    if (i == 0) g_off[NN] = NE;
}

__global__ __launch_bounds__(256) void k_fill(const int* __restrict__ ei) {
    int e = blockIdx.x * blockDim.x + threadIdx.x;
    if (e >= NE) return;
    int s = ei[e];
    int d = ei[NE + e];
    int slot = atomicAdd(&g_pos[d], 1);
    g_epair[slot] = make_int2(s, e);
}

// ---------------------------------------------------------------------------
// helpers: half-warp (16-lane) 128-bit row access
// ---------------------------------------------------------------------------
__device__ __forceinline__ void cvt8(const uint4& r, float* f) {
    __half2 h;
    float2 t;
    h = *reinterpret_cast<const __half2*>(&r.x); t = __half22float2(h); f[0] = t.x; f[1] = t.y;
    h = *reinterpret_cast<const __half2*>(&r.y); t = __half22float2(h); f[2] = t.x; f[3] = t.y;
    h = *reinterpret_cast<const __half2*>(&r.z); t = __half22float2(h); f[4] = t.x; f[5] = t.y;
    h = *reinterpret_cast<const __half2*>(&r.w); t = __half22float2(h); f[6] = t.x; f[7] = t.y;
}

__device__ __forceinline__ const uint4* rowq(const __half2* __restrict__ mx,
                                             int n, int q) {
    return (const uint4*)(mx + (size_t)n * 64) + q;
}

// ---------------------------------------------------------------------------
// fused node kernel: CSR mean-gather (into smem A) + tensor-core transform
//   out[n][o] = sum_k A[n][k] * Wcat[o][k] + bl[o]   (+relu), A = [mean | x]
// block: 256 thr = 8 warps; tile m=64 n=128 k=256; MMA warps: 2m x 4n.
// ---------------------------------------------------------------------------
#define AK 264
#define MT 64
#define SMEM_MMA ((MT + 128) * AK * (int)sizeof(__half))

__device__ __forceinline__ void ldsm4(uint32_t addr, uint32_t& r0, uint32_t& r1,
                                      uint32_t& r2, uint32_t& r3) {
    asm volatile("ldmatrix.sync.aligned.m8n8.x4.shared.b16 {%0,%1,%2,%3}, [%4];"
                 : "=r"(r0), "=r"(r1), "=r"(r2), "=r"(r3) : "r"(addr));
}

__device__ __forceinline__ void mma16816(float* c, const uint32_t* a,
                                         uint32_t b0, uint32_t b1) {
    asm volatile(
        "mma.sync.aligned.m16n8k16.row.col.f32.f16.f16.f32 "
        "{%0,%1,%2,%3}, {%4,%5,%6,%7}, {%8,%9}, {%0,%1,%2,%3};"
        : "+f"(c[0]), "+f"(c[1]), "+f"(c[2]), "+f"(c[3])
        : "r"(a[0]), "r"(a[1]), "r"(a[2]), "r"(a[3]), "r"(b0), "r"(b1));
}

template <bool RELU>
__global__ __launch_bounds__(256) void k_node_fused(const __half2* __restrict__ xh,
                                                    const __half* __restrict__ wcat,
                                                    const float* __restrict__ bl,
                                                    __half2* __restrict__ mout) {
    extern __shared__ __half sh[];
    __half* A_s = sh;                 // [MT][AK]: cols 0-127 = mean-agg, 128-255 = x
    __half* W_s = sh + MT * AK;       // [128][AK]

    int tid = threadIdx.x;
    int base = blockIdx.x * MT;
    int wid = tid >> 5, lane = tid & 31;
    int g = lane >> 4, q = lane & 15;

    // stage x half of A (q slots 16..31) and W
    for (int i = tid; i < MT * 16; i += 256) {
        int row = i >> 4, s = i & 15;
        int n = base + row;
        uint4 v = make_uint4(0, 0, 0, 0);
        if (n < NN) v = ((const uint4*)xh)[(size_t)n * 16 + s];
        *((uint4*)(A_s + (size_t)row * AK) + 16 + s) = v;
    }
    for (int i = tid; i < 128 * 32; i += 256) {
        int row = i >> 5, s = i & 31;
        *((uint4*)(W_s + (size_t)row * AK) + s) = ((const uint4*)wcat)[i];
    }

    // CSR mean-gather into agg half of A (q slots 0..15); warp handles 8 rows
#pragma unroll 1
    for (int rr = 0; rr < 8; rr++) {
        int row = wid * 8 + rr;
        int n = base + row;
        float acc[8];
#pragma unroll
        for (int j = 0; j < 8; j++) acc[j] = 0.0f;
        if (n < NN) {
            int beg = g_off[n], end = g_off[n + 1];
            int i = beg;
            for (; i + 8 <= end; i += 8) {
                int s0 = __ldg(&g_epair[i + 0 + g].x);
                int s1 = __ldg(&g_epair[i + 2 + g].x);
                int s2 = __ldg(&g_epair[i + 4 + g].x);
                int s3 = __ldg(&g_epair[i + 6 + g].x);
                uint4 r0 = __ldg(rowq(xh, s0, q));
                uint4 r1 = __ldg(rowq(xh, s1, q));
                uint4 r2 = __ldg(rowq(xh, s2, q));
                uint4 r3 = __ldg(rowq(xh, s3, q));
                float f0[8], f1[8], f2[8], f3[8];
                cvt8(r0, f0); cvt8(r1, f1); cvt8(r2, f2); cvt8(r3, f3);
#pragma unroll
                for (int j = 0; j < 8; j++) acc[j] += (f0[j] + f1[j]) + (f2[j] + f3[j]);
            }
            for (; i + 2 <= end; i += 2) {
                int s = __ldg(&g_epair[i + g].x);
                uint4 r = __ldg(rowq(xh, s, q));
                float f[8];
                cvt8(r, f);
#pragma unroll
                for (int j = 0; j < 8; j++) acc[j] += f[j];
            }
            if (i < end && g == 0) {   // odd tail: group 0 only
                int s = __ldg(&g_epair[i].x);
                uint4 r = __ldg(rowq(xh, s, q));
                float f[8];
                cvt8(r, f);
#pragma unroll
                for (int j = 0; j < 8; j++) acc[j] += f[j];
            }
        }
        // combine halves (disjoint edge sets)
#pragma unroll
        for (int j = 0; j < 8; j++) acc[j] += __shfl_xor_sync(0xFFFFFFFFu, acc[j], 16);

        if (g == 0) {
            float inv = (n < NN) ? g_inv[n] : 0.0f;
            uint4 hv;
            __half2 h;
            h = __floats2half2_rn(acc[0] * inv, acc[1] * inv); hv.x = *reinterpret_cast<unsigned*>(&h);
            h = __floats2half2_rn(acc[2] * inv, acc[3] * inv); hv.y = *reinterpret_cast<unsigned*>(&h);
            h = __floats2half2_rn(acc[4] * inv, acc[5] * inv); hv.z = *reinterpret_cast<unsigned*>(&h);
            h = __floats2half2_rn(acc[6] * inv, acc[7] * inv); hv.w = *reinterpret_cast<unsigned*>(&h);
            *((uint4*)(A_s + (size_t)row * AK) + q) = hv;
        }
    }
    __syncthreads();

    // ----- MMA phase (unchanged from verified k_node_mma) -----
    int wm = wid & 1, wn = wid >> 1;   // warp m (x2), warp n (x4)

    int lrow = (lane & 7) + (((lane >> 3) & 1) << 3);
    int lkh  = (lane >> 4) << 3;
    uint32_t a_base[2];
#pragma unroll
    for (int mt = 0; mt < 2; mt++)
        a_base[mt] = (uint32_t)__cvta_generic_to_shared(
            A_s + (size_t)(wm * 32 + mt * 16 + lrow) * AK + lkh);

    int bnrow = (lane & 7) + (((lane >> 4) & 1) << 3);
    int bkh   = ((lane >> 3) & 1) << 3;
    uint32_t b_base[2];
#pragma unroll
    for (int gp = 0; gp < 2; gp++)
        b_base[gp] = (uint32_t)__cvta_generic_to_shared(
            W_s + (size_t)(wn * 32 + gp * 16 + bnrow) * AK + bkh);

    float acc[2][4][4];
#pragma unroll
    for (int mt = 0; mt < 2; mt++)
#pragma unroll
        for (int gg = 0; gg < 4; gg++)
#pragma unroll
            for (int j = 0; j < 4; j++) acc[mt][gg][j] = 0.0f;

#pragma unroll 4
    for (int kc = 0; kc < 16; kc++) {
        uint32_t koff = kc * 32;
        uint32_t a[2][4];
        ldsm4(a_base[0] + koff, a[0][0], a[0][1], a[0][2], a[0][3]);
        ldsm4(a_base[1] + koff, a[1][0], a[1][1], a[1][2], a[1][3]);
#pragma unroll
        for (int gp = 0; gp < 2; gp++) {
            uint32_t b0, b1, b2, b3;
            ldsm4(b_base[gp] + koff, b0, b1, b2, b3);
#pragma unroll
            for (int mt = 0; mt < 2; mt++) {
                mma16816(acc[mt][gp * 2 + 0], a[mt], b0, b1);
                mma16816(acc[mt][gp * 2 + 1], a[mt], b2, b3);
            }
        }
    }

    // epilogue: bias + relu + fp16 store
    int r_in = lane >> 2;
    int cpair = (lane & 3) * 2;
#pragma unroll
    for (int mt = 0; mt < 2; mt++) {
#pragma unroll
        for (int gg = 0; gg < 4; gg++) {
            int col = wn * 32 + gg * 8 + cpair;
            float2 b2 = *(const float2*)(bl + col);
            float x0 = acc[mt][gg][0] + b2.x;
            float y0 = acc[mt][gg][1] + b2.y;
            float x1 = acc[mt][gg][2] + b2.x;
            float y1 = acc[mt][gg][3] + b2.y;
            if (RELU) {
                x0 = fmaxf(x0, 0.0f); y0 = fmaxf(y0, 0.0f);
                x1 = fmaxf(x1, 0.0f); y1 = fmaxf(y1, 0.0f);
            }
            int row0 = base + wm * 32 + mt * 16 + r_in;
            int row1 = row0 + 8;
            if (row0 < NN) mout[(size_t)row0 * 64 + (col >> 1)] = __floats2half2_rn(x0, y0);
            if (row1 < NN) mout[(size_t)row1 * 64 + (col >> 1)] = __floats2half2_rn(x1, y1);
        }
    }
}

// ---------------------------------------------------------------------------
// edge output via CSR: one warp per dst node, half-warp per edge (LDG.128).
// ---------------------------------------------------------------------------
__device__ __forceinline__ float half_red(float v) {
#pragma unroll
    for (int off = 8; off; off >>= 1) v += __shfl_xor_sync(0xFFFFFFFFu, v, off);
    return v;   // lanes 0 and 16 hold their group's sum
}

__device__ __forceinline__ float dot8(const float* a, const float* b) {
    return (a[0] * b[0] + a[1] * b[1]) + (a[2] * b[2] + a[3] * b[3])
         + (a[4] * b[4] + a[5] * b[5]) + (a[6] * b[6] + a[7] * b[7]);
}

__global__ __launch_bounds__(256) void k_edge_csr(const __half2* __restrict__ mx,
                                                  float* __restrict__ out) {
    int n = (blockIdx.x * blockDim.x + threadIdx.x) >> 5;
    int lane = threadIdx.x & 31;
    if (n >= NN) return;
    int q = lane & 15;
    int g = lane >> 4;
    int beg = g_off[n], end = g_off[n + 1];
    if (beg == end) return;

    float bf[8];
    {
        uint4 r = __ldg(rowq(mx, n, q));
        cvt8(r, bf);
    }

    int i = beg;
    for (; i + 8 <= end; i += 8) {
        int2 p0 = __ldg(&g_epair[i + 0 + g]);
        int2 p1 = __ldg(&g_epair[i + 2 + g]);
        int2 p2 = __ldg(&g_epair[i + 4 + g]);
        int2 p3 = __ldg(&g_epair[i + 6 + g]);
        uint4 r0 = __ldg(rowq(mx, p0.x, q));
        uint4 r1 = __ldg(rowq(mx, p1.x, q));
        uint4 r2 = __ldg(rowq(mx, p2.x, q));
        uint4 r3 = __ldg(rowq(mx, p3.x, q));
        float f[8];
        cvt8(r0, f); float v0 = half_red(dot8(f, bf));
        cvt8(r1, f); float v1 = half_red(dot8(f, bf));
        cvt8(r2, f); float v2 = half_red(dot8(f, bf));
        cvt8(r3, f); float v3 = half_red(dot8(f, bf));
        if (q == 0) {
            out[p0.y] = v0;
            out[p1.y] = v1;
            out[p2.y] = v2;
            out[p3.y] = v3;
        }
    }
    for (; i + 2 <= end; i += 2) {
        int2 p = __ldg(&g_epair[i + g]);
        uint4 r = __ldg(rowq(mx, p.x, q));
        float f[8];
        cvt8(r, f);
        float v = half_red(dot8(f, bf));
        if (q == 0) out[p.y] = v;
    }
    if (i < end) {   // odd tail: both groups compute same edge; lane 0 writes
        int2 p = __ldg(&g_epair[i]);
        uint4 r = __ldg(rowq(mx, p.x, q));
        float f[8];
        cvt8(r, f);
        float v = half_red(dot8(f, bf));
        if (lane == 0) out[p.y] = v;
    }
}

// ---------------------------------------------------------------------------
extern "C" void kernel_launch(void* const* d_in, const int* in_sizes, int n_in,
                              void* d_out, int out_size) {
    const int* nid = (const int*)d_in[0];
    const int* ei  = (const int*)d_in[1];
    const float* emb = (const float*)d_in[2];
    const float* Wl1 = (const float*)d_in[3];
    const float* bl1 = (const float*)d_in[4];
    const float* Wr1 = (const float*)d_in[5];
    const float* Wl2 = (const float*)d_in[6];
    const float* bl2 = (const float*)d_in[7];
    const float* Wr2 = (const float*)d_in[8];
    float* out = (float*)d_out;

    cudaFuncSetAttribute(k_node_fused<true>,
                         cudaFuncAttributeMaxDynamicSharedMemorySize, SMEM_MMA);
    cudaFuncSetAttribute(k_node_fused<false>,
                         cudaFuncAttributeMaxDynamicSharedMemorySize, SMEM_MMA);

    __half2 *pmx, *pmh;
    __half *pw1, *pw2;
    cudaGetSymbolAddress((void**)&pmx, g_mx);
    cudaGetSymbolAddress((void**)&pmh, g_mh);
    cudaGetSymbolAddress((void**)&pw1, g_w1);
    cudaGetSymbolAddress((void**)&pw2, g_w2);

    int gridI    = (NN * 64 + 255) / 256;
    int gridE    = (NE + 255) / 256;
    int gridNW   = (NN * 32 + 255) / 256;   // warp-per-node
    int gridMMA  = (NN + MT - 1) / MT;

    // preprocessing: features/weights, CSR build (count -> lookback scan -> fill)
    k_prep<<<gridI, 256>>>(emb, nid, Wl1, Wr1, Wl2, Wr2);
    k_count<<<gridE, 256>>>(ei + NE);
    k_scan<<<NBLK, SCAN_B>>>();
    k_fill<<<gridE, 256>>>(ei);

    // Layer 1 (gather + transform fused)
    k_node_fused<true><<<gridMMA, 256, SMEM_MMA>>>(pmx, pw1, bl1, pmh);

    // Layer 2 (output overwrites g_mx)
    k_node_fused<false><<<gridMMA, 256, SMEM_MMA>>>(pmh, pw2, bl2, pmx);

    // Edge classifier
    k_edge_csr<<<gridNW, 256>>>(pmx, out);
}

// round 11
// speedup vs baseline: 1.3097x; 1.3097x over previous
#include <cuda_runtime.h>
#include <cuda.h>
#include <cuda_fp16.h>

#define NN 50000
#define NE 800000
#define H  128
#define SCAN_B 1024
#define NBLK ((NN + SCAN_B - 1) / SCAN_B)   // 49

// Scratch (device globals; no allocation allowed)
__device__ float   g_inv[NN];
__device__ int     g_cnt[NN];               // zero at entry (static init + scan resets)
__device__ int     g_off[NN + 1];
__device__ int     g_pos[NN];
__device__ int     g_flag[NBLK];            // lookback status: 0 inv, 1 agg, 2 prefix
__device__ int     g_aggv[NBLK];
__device__ int     g_pref[NBLK];
__device__ int2    g_epair[NE];             // {src, edge_id} bucketed by dst
__device__ __align__(16) __half2 g_mx[NN * 64];   // x0 mirror; later final features
__device__ __align__(16) __half2 g_mh[NN * 64];   // layer-1 output
__device__ __align__(16) __half2 g_aggh[NN * 64]; // aggregation output (fp16)
__device__ __align__(16) __half  g_w1[H * 2 * H]; // [o][k] concat: k<128 Wl, k>=128 Wr
__device__ __align__(16) __half  g_w2[H * 2 * H];

// ---------------------------------------------------------------------------
// prep: gather x0 mirror, convert weights, count edges per dst, reset flags
// (g_cnt is zero at entry: static zero first call, reset by k_scan afterwards)
// ---------------------------------------------------------------------------
__global__ __launch_bounds__(256) void k_prep(const float* __restrict__ emb,
                                              const int* __restrict__ nid,
                                              const int* __restrict__ dst,
                                              const float* __restrict__ Wl1,
                                              const float* __restrict__ Wr1,
                                              const float* __restrict__ Wl2,
                                              const float* __restrict__ Wr2) {
    int i = blockIdx.x * blockDim.x + threadIdx.x;   // half2 index
    if (i < NN * 64) {
        int r = i >> 6;
        int n = nid[r];
        float2 v = ((const float2*)(emb + (size_t)n * H))[i & 63];
        g_mx[i] = __floats2half2_rn(v.x, v.y);
    }
    if (i < H * 2 * H) {
        int o = i >> 8, k = i & 255;
        g_w1[i] = __float2half((k < H) ? Wl1[o * H + k] : Wr1[o * H + (k - H)]);
        g_w2[i] = __float2half((k < H) ? Wl2[o * H + k] : Wr2[o * H + (k - H)]);
    }
    if (i < NBLK) g_flag[i] = 0;
    if (i < NE) atomicAdd(&g_cnt[dst[i]], 1);
}

// ---------------------------------------------------------------------------
// single-pass decoupled-lookback scan: g_cnt -> g_off/g_pos/g_inv; resets g_cnt
// (49 blocks <= #SMs, all co-resident -> lookback is deadlock-free)
// ---------------------------------------------------------------------------
__global__ __launch_bounds__(SCAN_B) void k_scan() {
    __shared__ int warp_sums[32];
    __shared__ int s_excl;
    int tid = threadIdx.x;
    int lane = tid & 31, w = tid >> 5;
    int b = blockIdx.x;
    int i = b * SCAN_B + tid;
    int v = (i < NN) ? g_cnt[i] : 0;
    int xs = v;
#pragma unroll
    for (int off = 1; off < 32; off <<= 1) {
        int t = __shfl_up_sync(0xFFFFFFFFu, xs, off);
        if (lane >= off) xs += t;
    }
    if (lane == 31) warp_sums[w] = xs;
    __syncthreads();
    if (w == 0) {
        int s = warp_sums[lane];
#pragma unroll
        for (int off = 1; off < 32; off <<= 1) {
            int t = __shfl_up_sync(0xFFFFFFFFu, s, off);
            if (lane >= off) s += t;
        }
        warp_sums[lane] = s;
    }
    __syncthreads();
    int incl = xs + (w > 0 ? warp_sums[w - 1] : 0);
    int total = warp_sums[31];

    if (tid == 0) {
        volatile int* vflag = g_flag;
        volatile int* vaggv = g_aggv;
        volatile int* vpref = g_pref;
        if (b == 0) {
            vpref[0] = total;
            __threadfence();
            vflag[0] = 2;
            s_excl = 0;
        } else {
            vaggv[b] = total;
            __threadfence();
            vflag[b] = 1;
            int excl = 0;
            for (int j = b - 1; j >= 0;) {
                int f;
                do { f = vflag[j]; } while (f == 0);
                if (f == 2) { excl += vpref[j]; break; }
                excl += vaggv[j];
                j--;
            }
            vpref[b] = excl + total;
            __threadfence();
            vflag[b] = 2;
            s_excl = excl;
        }
    }
    __syncthreads();
    if (i < NN) {
        int e = incl - v + s_excl;
        g_off[i] = e;
        g_pos[i] = e;
        g_inv[i] = 1.0f / (float)max(v, 1);
        g_cnt[i] = 0;            // restore invariant for next call
    }
    if (i == 0) g_off[NN] = NE;
}

__global__ __launch_bounds__(256) void k_fill(const int* __restrict__ ei) {
    int e = blockIdx.x * blockDim.x + threadIdx.x;
    if (e >= NE) return;
    int s = ei[e];
    int d = ei[NE + e];
    int slot = atomicAdd(&g_pos[d], 1);
    g_epair[slot] = make_int2(s, e);
}

// ---------------------------------------------------------------------------
// helpers: half-warp (16-lane) 128-bit row access
// ---------------------------------------------------------------------------
__device__ __forceinline__ void cvt8(const uint4& r, float* f) {
    __half2 h;
    float2 t;
    h = *reinterpret_cast<const __half2*>(&r.x); t = __half22float2(h); f[0] = t.x; f[1] = t.y;
    h = *reinterpret_cast<const __half2*>(&r.y); t = __half22float2(h); f[2] = t.x; f[3] = t.y;
    h = *reinterpret_cast<const __half2*>(&r.z); t = __half22float2(h); f[4] = t.x; f[5] = t.y;
    h = *reinterpret_cast<const __half2*>(&r.w); t = __half22float2(h); f[6] = t.x; f[7] = t.y;
}

__device__ __forceinline__ const uint4* rowq(const __half2* __restrict__ mx,
                                             int n, int q) {
    return (const uint4*)(mx + (size_t)n * 64) + q;
}

// ---------------------------------------------------------------------------
// aggregate: one warp per node, half-warp per edge row (LDG.128).
// ---------------------------------------------------------------------------
__global__ __launch_bounds__(256) void k_aggr(const __half2* __restrict__ mx) {
    int n = (blockIdx.x * blockDim.x + threadIdx.x) >> 5;
    int lane = threadIdx.x & 31;
    if (n >= NN) return;
    int g = lane >> 4, q = lane & 15;
    int beg = g_off[n], end = g_off[n + 1];
    float acc[8];
#pragma unroll
    for (int j = 0; j < 8; j++) acc[j] = 0.0f;

    int i = beg;
    for (; i + 8 <= end; i += 8) {
        int s0 = __ldg(&g_epair[i + 0 + g].x);
        int s1 = __ldg(&g_epair[i + 2 + g].x);
        int s2 = __ldg(&g_epair[i + 4 + g].x);
        int s3 = __ldg(&g_epair[i + 6 + g].x);
        uint4 r0 = __ldg(rowq(mx, s0, q));
        uint4 r1 = __ldg(rowq(mx, s1, q));
        uint4 r2 = __ldg(rowq(mx, s2, q));
        uint4 r3 = __ldg(rowq(mx, s3, q));
        float f0[8], f1[8], f2[8], f3[8];
        cvt8(r0, f0); cvt8(r1, f1); cvt8(r2, f2); cvt8(r3, f3);
#pragma unroll
        for (int j = 0; j < 8; j++) acc[j] += (f0[j] + f1[j]) + (f2[j] + f3[j]);
    }
    for (; i + 2 <= end; i += 2) {
        int s = __ldg(&g_epair[i + g].x);
        uint4 r = __ldg(rowq(mx, s, q));
        float f[8];
        cvt8(r, f);
#pragma unroll
        for (int j = 0; j < 8; j++) acc[j] += f[j];
    }
    if (i < end && g == 0) {   // odd tail: group 0 only
        int s = __ldg(&g_epair[i].x);
        uint4 r = __ldg(rowq(mx, s, q));
        float f[8];
        cvt8(r, f);
#pragma unroll
        for (int j = 0; j < 8; j++) acc[j] += f[j];
    }

    // combine the two halves (disjoint edge sets)
#pragma unroll
    for (int j = 0; j < 8; j++) acc[j] += __shfl_xor_sync(0xFFFFFFFFu, acc[j], 16);

    if (g == 0) {
        float inv = g_inv[n];
        uint4 hv;
        __half2 h;
        h = __floats2half2_rn(acc[0] * inv, acc[1] * inv); hv.x = *reinterpret_cast<unsigned*>(&h);
        h = __floats2half2_rn(acc[2] * inv, acc[3] * inv); hv.y = *reinterpret_cast<unsigned*>(&h);
        h = __floats2half2_rn(acc[4] * inv, acc[5] * inv); hv.z = *reinterpret_cast<unsigned*>(&h);
        h = __floats2half2_rn(acc[6] * inv, acc[7] * inv); hv.w = *reinterpret_cast<unsigned*>(&h);
        ((uint4*)(g_aggh + (size_t)n * 64))[q] = hv;
    }
}

// ---------------------------------------------------------------------------
// node transform via tensor cores, persistent blocks:
//   out[n][o] = sum_k A[n][k] * Wcat[o][k] + bl[o]   (+relu), A = [agg | x]
// tile m=64 n=128 k=256; 8 warps (2m x 4n); W staged once per block.
// ---------------------------------------------------------------------------
#define AK 264
#define MT 64
#define NT ((NN + MT - 1) / MT)   // 782 tiles
#define GRID_MMA 296
#define SMEM_MMA ((MT + 128) * AK * (int)sizeof(__half))

__device__ __forceinline__ void ldsm4(uint32_t addr, uint32_t& r0, uint32_t& r1,
                                      uint32_t& r2, uint32_t& r3) {
    asm volatile("ldmatrix.sync.aligned.m8n8.x4.shared.b16 {%0,%1,%2,%3}, [%4];"
                 : "=r"(r0), "=r"(r1), "=r"(r2), "=r"(r3) : "r"(addr));
}

__device__ __forceinline__ void mma16816(float* c, const uint32_t* a,
                                         uint32_t b0, uint32_t b1) {
    asm volatile(
        "mma.sync.aligned.m16n8k16.row.col.f32.f16.f16.f32 "
        "{%0,%1,%2,%3}, {%4,%5,%6,%7}, {%8,%9}, {%0,%1,%2,%3};"
        : "+f"(c[0]), "+f"(c[1]), "+f"(c[2]), "+f"(c[3])
        : "r"(a[0]), "r"(a[1]), "r"(a[2]), "r"(a[3]), "r"(b0), "r"(b1));
}

template <bool RELU>
__global__ __launch_bounds__(256) void k_node_mma(const __half2* __restrict__ aggh,
                                                  const __half2* __restrict__ xh,
                                                  const __half* __restrict__ wcat,
                                                  const float* __restrict__ bl,
                                                  __half2* __restrict__ mout) {
    extern __shared__ __half sh[];
    __half* A_s = sh;                 // [MT][AK]
    __half* W_s = sh + MT * AK;       // [128][AK]

    int tid = threadIdx.x;
    int wid = tid >> 5, lane = tid & 31;
    int wm = wid & 1, wn = wid >> 1;   // warp m (x2), warp n (x4)

    // stage W once
    for (int i = tid; i < 128 * 32; i += 256) {
        int row = i >> 5, s = i & 31;
        *((uint4*)(W_s + (size_t)row * AK) + s) = ((const uint4*)wcat)[i];
    }

    // per-lane ldmatrix addressing (tile-invariant)
    int lrow = (lane & 7) + (((lane >> 3) & 1) << 3);
    int lkh  = (lane >> 4) << 3;
    uint32_t a_base[2];
#pragma unroll
    for (int mt = 0; mt < 2; mt++)
        a_base[mt] = (uint32_t)__cvta_generic_to_shared(
            A_s + (size_t)(wm * 32 + mt * 16 + lrow) * AK + lkh);

    int bnrow = (lane & 7) + (((lane >> 4) & 1) << 3);
    int bkh   = ((lane >> 3) & 1) << 3;
    uint32_t b_base[2];
#pragma unroll
    for (int gp = 0; gp < 2; gp++)
        b_base[gp] = (uint32_t)__cvta_generic_to_shared(
            W_s + (size_t)(wn * 32 + gp * 16 + bnrow) * AK + bkh);

    int r_in = lane >> 2;
    int cpair = (lane & 3) * 2;

    for (int t = blockIdx.x; t < NT; t += GRID_MMA) {
        int base = t * MT;
        __syncthreads();   // previous iteration's MMA reads of A_s done

        // stage A = [agg | x]
        for (int i = tid; i < MT * 32; i += 256) {
            int row = i >> 5, s = i & 31;
            int n = base + row;
            uint4 v = make_uint4(0, 0, 0, 0);
            if (n < NN)
                v = (s < 16) ? ((const uint4*)aggh)[(size_t)n * 16 + s]
                             : ((const uint4*)xh)[(size_t)n * 16 + (s - 16)];
            *((uint4*)(A_s + (size_t)row * AK) + s) = v;
        }
        __syncthreads();

        float acc[2][4][4];
#pragma unroll
        for (int mt = 0; mt < 2; mt++)
#pragma unroll
            for (int g = 0; g < 4; g++)
#pragma unroll
                for (int j = 0; j < 4; j++) acc[mt][g][j] = 0.0f;

#pragma unroll 4
        for (int kc = 0; kc < 16; kc++) {
            uint32_t koff = kc * 32;
            uint32_t a[2][4];
            ldsm4(a_base[0] + koff, a[0][0], a[0][1], a[0][2], a[0][3]);
            ldsm4(a_base[1] + koff, a[1][0], a[1][1], a[1][2], a[1][3]);
#pragma unroll
            for (int gp = 0; gp < 2; gp++) {
                uint32_t b0, b1, b2, b3;
                ldsm4(b_base[gp] + koff, b0, b1, b2, b3);
#pragma unroll
                for (int mt = 0; mt < 2; mt++) {
                    mma16816(acc[mt][gp * 2 + 0], a[mt], b0, b1);
                    mma16816(acc[mt][gp * 2 + 1], a[mt], b2, b3);
                }
            }
        }

        // epilogue: bias + relu + fp16 store
#pragma unroll
        for (int mt = 0; mt < 2; mt++) {
#pragma unroll
            for (int g = 0; g < 4; g++) {
                int col = wn * 32 + g * 8 + cpair;
                float2 b2 = *(const float2*)(bl + col);
                float x0 = acc[mt][g][0] + b2.x;
                float y0 = acc[mt][g][1] + b2.y;
                float x1 = acc[mt][g][2] + b2.x;
                float y1 = acc[mt][g][3] + b2.y;
                if (RELU) {
                    x0 = fmaxf(x0, 0.0f); y0 = fmaxf(y0, 0.0f);
                    x1 = fmaxf(x1, 0.0f); y1 = fmaxf(y1, 0.0f);
                }
                int row0 = base + wm * 32 + mt * 16 + r_in;
                int row1 = row0 + 8;
                if (row0 < NN) mout[(size_t)row0 * 64 + (col >> 1)] = __floats2half2_rn(x0, y0);
                if (row1 < NN) mout[(size_t)row1 * 64 + (col >> 1)] = __floats2half2_rn(x1, y1);
            }
        }
    }
}

// ---------------------------------------------------------------------------
// edge output via CSR: one warp per dst node, half-warp per edge (LDG.128).
// ---------------------------------------------------------------------------
__device__ __forceinline__ float half_red(float v) {
#pragma unroll
    for (int off = 8; off; off >>= 1) v += __shfl_xor_sync(0xFFFFFFFFu, v, off);
    return v;   // lanes 0 and 16 hold their group's sum
}

__device__ __forceinline__ float dot8(const float* a, const float* b) {
    return (a[0] * b[0] + a[1] * b[1]) + (a[2] * b[2] + a[3] * b[3])
         + (a[4] * b[4] + a[5] * b[5]) + (a[6] * b[6] + a[7] * b[7]);
}

__global__ __launch_bounds__(256) void k_edge_csr(const __half2* __restrict__ mx,
                                                  float* __restrict__ out) {
    int n = (blockIdx.x * blockDim.x + threadIdx.x) >> 5;
    int lane = threadIdx.x & 31;
    if (n >= NN) return;
    int q = lane & 15;
    int g = lane >> 4;
    int beg = g_off[n], end = g_off[n + 1];
    if (beg == end) return;

    float bf[8];
    {
        uint4 r = __ldg(rowq(mx, n, q));
        cvt8(r, bf);
    }

    int i = beg;
    for (; i + 8 <= end; i += 8) {
        int2 p0 = __ldg(&g_epair[i + 0 + g]);
        int2 p1 = __ldg(&g_epair[i + 2 + g]);
        int2 p2 = __ldg(&g_epair[i + 4 + g]);
        int2 p3 = __ldg(&g_epair[i + 6 + g]);
        uint4 r0 = __ldg(rowq(mx, p0.x, q));
        uint4 r1 = __ldg(rowq(mx, p1.x, q));
        uint4 r2 = __ldg(rowq(mx, p2.x, q));
        uint4 r3 = __ldg(rowq(mx, p3.x, q));
        float f[8];
        cvt8(r0, f); float v0 = half_red(dot8(f, bf));
        cvt8(r1, f); float v1 = half_red(dot8(f, bf));
        cvt8(r2, f); float v2 = half_red(dot8(f, bf));
        cvt8(r3, f); float v3 = half_red(dot8(f, bf));
        if (q == 0) {
            out[p0.y] = v0;
            out[p1.y] = v1;
            out[p2.y] = v2;
            out[p3.y] = v3;
        }
    }
    for (; i + 2 <= end; i += 2) {
        int2 p = __ldg(&g_epair[i + g]);
        uint4 r = __ldg(rowq(mx, p.x, q));
        float f[8];
        cvt8(r, f);
        float v = half_red(dot8(f, bf));
        if (q == 0) out[p.y] = v;
    }
    if (i < end) {   // odd tail: both groups compute same edge; lane 0 writes
        int2 p = __ldg(&g_epair[i]);
        uint4 r = __ldg(rowq(mx, p.x, q));
        float f[8];
        cvt8(r, f);
        float v = half_red(dot8(f, bf));
        if (lane == 0) out[p.y] = v;
    }
}

// ---------------------------------------------------------------------------
extern "C" void kernel_launch(void* const* d_in, const int* in_sizes, int n_in,
                              void* d_out, int out_size) {
    const int* nid = (const int*)d_in[0];
    const int* ei  = (const int*)d_in[1];
    const float* emb = (const float*)d_in[2];
    const float* Wl1 = (const float*)d_in[3];
    const float* bl1 = (const float*)d_in[4];
    const float* Wr1 = (const float*)d_in[5];
    const float* Wl2 = (const float*)d_in[6];
    const float* bl2 = (const float*)d_in[7];
    const float* Wr2 = (const float*)d_in[8];
    float* out = (float*)d_out;

    cudaFuncSetAttribute(k_node_mma<true>,
                         cudaFuncAttributeMaxDynamicSharedMemorySize, SMEM_MMA);
    cudaFuncSetAttribute(k_node_mma<false>,
                         cudaFuncAttributeMaxDynamicSharedMemorySize, SMEM_MMA);

    __half2 *pmx, *pmh, *pagg;
    __half *pw1, *pw2;
    cudaGetSymbolAddress((void**)&pmx, g_mx);
    cudaGetSymbolAddress((void**)&pmh, g_mh);
    cudaGetSymbolAddress((void**)&pagg, g_aggh);
    cudaGetSymbolAddress((void**)&pw1, g_w1);
    cudaGetSymbolAddress((void**)&pw2, g_w2);

    int gridI  = (NN * 64 + 255) / 256;
    int gridE  = (NE + 255) / 256;
    int gridNW = (NN * 32 + 255) / 256;   // warp-per-node

    // preprocessing: features/weights/count fused; lookback scan; CSR fill
    k_prep<<<gridI, 256>>>(emb, nid, ei + NE, Wl1, Wr1, Wl2, Wr2);
    k_scan<<<NBLK, SCAN_B>>>();
    k_fill<<<gridE, 256>>>(ei);

    // Layer 1
    k_aggr<<<gridNW, 256>>>(pmx);
    k_node_mma<true><<<GRID_MMA, 256, SMEM_MMA>>>(pagg, pmx, pw1, bl1, pmh);

    // Layer 2 (output overwrites g_mx)
    k_aggr<<<gridNW, 256>>>(pmh);
    k_node_mma<false><<<GRID_MMA, 256, SMEM_MMA>>>(pagg, pmh, pw2, bl2, pmx);

    // Edge classifier
    k_edge_csr<<<gridNW, 256>>>(pmx, out);
}

// round 12
// speedup vs baseline: 1.3616x; 1.0396x over previous
#include <cuda_runtime.h>
#include <cuda.h>
#include <cuda_fp16.h>

#define NN 50000
#define NE 800000
#define H  128
#define SCAN_B 1024
#define NBLK ((NN + SCAN_B - 1) / SCAN_B)   // 49

// Scratch (device globals; no allocation allowed)
__device__ float   g_inv[NN];
__device__ int     g_cnt[NN];               // zero at entry (static init + scan resets)
__device__ int     g_off[NN + 1];
__device__ int     g_pos[NN];
__device__ int     g_flag[NBLK];            // lookback status: 0 inv, 1 agg, 2 prefix
__device__ int     g_aggv[NBLK];
__device__ int     g_pref[NBLK];
__device__ int2    g_epair[NE];             // {src, edge_id} bucketed by dst
__device__ __align__(16) __half2 g_mx[NN * 64];   // x0 mirror; later final features
__device__ __align__(16) __half2 g_mh[NN * 64];   // layer-1 output
__device__ __align__(16) __half2 g_aggh[NN * 64]; // aggregation output (fp16)
__device__ __align__(16) __half  g_w1[H * 2 * H]; // [o][k] concat: k<128 Wl, k>=128 Wr
__device__ __align__(16) __half  g_w2[H * 2 * H];

// ---------------------------------------------------------------------------
// prep: gather x0 mirror, convert weights, count edges per dst, reset flags
// (g_cnt is zero at entry: static zero first call, reset by k_scan afterwards)
// ---------------------------------------------------------------------------
__global__ __launch_bounds__(256) void k_prep(const float* __restrict__ emb,
                                              const int* __restrict__ nid,
                                              const int* __restrict__ dst,
                                              const float* __restrict__ Wl1,
                                              const float* __restrict__ Wr1,
                                              const float* __restrict__ Wl2,
                                              const float* __restrict__ Wr2) {
    int i = blockIdx.x * blockDim.x + threadIdx.x;   // half2 index
    if (i < NN * 64) {
        int r = i >> 6;
        int n = nid[r];
        float2 v = ((const float2*)(emb + (size_t)n * H))[i & 63];
        g_mx[i] = __floats2half2_rn(v.x, v.y);
    }
    if (i < H * 2 * H) {
        int o = i >> 8, k = i & 255;
        g_w1[i] = __float2half((k < H) ? Wl1[o * H + k] : Wr1[o * H + (k - H)]);
        g_w2[i] = __float2half((k < H) ? Wl2[o * H + k] : Wr2[o * H + (k - H)]);
    }
    if (i < NBLK) g_flag[i] = 0;
    if (i < NE) atomicAdd(&g_cnt[dst[i]], 1);
}

// ---------------------------------------------------------------------------
// single-pass decoupled-lookback scan: g_cnt -> g_off/g_pos/g_inv; resets g_cnt
// (49 blocks <= #SMs, all co-resident -> lookback is deadlock-free)
// ---------------------------------------------------------------------------
__global__ __launch_bounds__(SCAN_B) void k_scan() {
    __shared__ int warp_sums[32];
    __shared__ int s_excl;
    int tid = threadIdx.x;
    int lane = tid & 31, w = tid >> 5;
    int b = blockIdx.x;
    int i = b * SCAN_B + tid;
    int v = (i < NN) ? g_cnt[i] : 0;
    int xs = v;
#pragma unroll
    for (int off = 1; off < 32; off <<= 1) {
        int t = __shfl_up_sync(0xFFFFFFFFu, xs, off);
        if (lane >= off) xs += t;
    }
    if (lane == 31) warp_sums[w] = xs;
    __syncthreads();
    if (w == 0) {
        int s = warp_sums[lane];
#pragma unroll
        for (int off = 1; off < 32; off <<= 1) {
            int t = __shfl_up_sync(0xFFFFFFFFu, s, off);
            if (lane >= off) s += t;
        }
        warp_sums[lane] = s;
    }
    __syncthreads();
    int incl = xs + (w > 0 ? warp_sums[w - 1] : 0);
    int total = warp_sums[31];

    if (tid == 0) {
        volatile int* vflag = g_flag;
        volatile int* vaggv = g_aggv;
        volatile int* vpref = g_pref;
        if (b == 0) {
            vpref[0] = total;
            __threadfence();
            vflag[0] = 2;
            s_excl = 0;
        } else {
            vaggv[b] = total;
            __threadfence();
            vflag[b] = 1;
            int excl = 0;
            for (int j = b - 1; j >= 0;) {
                int f;
                do { f = vflag[j]; } while (f == 0);
                if (f == 2) { excl += vpref[j]; break; }
                excl += vaggv[j];
                j--;
            }
            vpref[b] = excl + total;
            __threadfence();
            vflag[b] = 2;
            s_excl = excl;
        }
    }
    __syncthreads();
    if (i < NN) {
        int e = incl - v + s_excl;
        g_off[i] = e;
        g_pos[i] = e;
        g_inv[i] = 1.0f / (float)max(v, 1);
        g_cnt[i] = 0;            // restore invariant for next call
    }
    if (i == 0) g_off[NN] = NE;
}

__global__ __launch_bounds__(256) void k_fill(const int* __restrict__ ei) {
    int e = blockIdx.x * blockDim.x + threadIdx.x;
    if (e >= NE) return;
    int s = ei[e];
    int d = ei[NE + e];
    int slot = atomicAdd(&g_pos[d], 1);
    g_epair[slot] = make_int2(s, e);
}

// ---------------------------------------------------------------------------
// helpers: half-warp (16-lane) 128-bit row access
// ---------------------------------------------------------------------------
__device__ __forceinline__ void cvt8(const uint4& r, float* f) {
    __half2 h;
    float2 t;
    h = *reinterpret_cast<const __half2*>(&r.x); t = __half22float2(h); f[0] = t.x; f[1] = t.y;
    h = *reinterpret_cast<const __half2*>(&r.y); t = __half22float2(h); f[2] = t.x; f[3] = t.y;
    h = *reinterpret_cast<const __half2*>(&r.z); t = __half22float2(h); f[4] = t.x; f[5] = t.y;
    h = *reinterpret_cast<const __half2*>(&r.w); t = __half22float2(h); f[6] = t.x; f[7] = t.y;
}

__device__ __forceinline__ const uint4* rowq(const __half2* __restrict__ mx,
                                             int n, int q) {
    return (const uint4*)(mx + (size_t)n * 64) + q;
}

__device__ __forceinline__ __half2 h2(unsigned u) {
    return *reinterpret_cast<__half2*>(&u);
}

// ---------------------------------------------------------------------------
// aggregate: one warp per node, half-warp per edge row (LDG.128).
// main loop sums 4 rows pairwise in fp16 (HADD2 tree), then fp32-accumulates.
// ---------------------------------------------------------------------------
__global__ __launch_bounds__(256) void k_aggr(const __half2* __restrict__ mx) {
    int n = (blockIdx.x * blockDim.x + threadIdx.x) >> 5;
    int lane = threadIdx.x & 31;
    if (n >= NN) return;
    int g = lane >> 4, q = lane & 15;
    int beg = g_off[n], end = g_off[n + 1];
    float acc[8];
#pragma unroll
    for (int j = 0; j < 8; j++) acc[j] = 0.0f;

    int i = beg;
    for (; i + 8 <= end; i += 8) {
        int s0 = __ldg(&g_epair[i + 0 + g].x);
        int s1 = __ldg(&g_epair[i + 2 + g].x);
        int s2 = __ldg(&g_epair[i + 4 + g].x);
        int s3 = __ldg(&g_epair[i + 6 + g].x);
        uint4 r0 = __ldg(rowq(mx, s0, q));
        uint4 r1 = __ldg(rowq(mx, s1, q));
        uint4 r2 = __ldg(rowq(mx, s2, q));
        uint4 r3 = __ldg(rowq(mx, s3, q));
        // pairwise fp16 tree per component, single convert, fp32 accumulate
        __half2 sx = __hadd2(__hadd2(h2(r0.x), h2(r1.x)), __hadd2(h2(r2.x), h2(r3.x)));
        __half2 sy = __hadd2(__hadd2(h2(r0.y), h2(r1.y)), __hadd2(h2(r2.y), h2(r3.y)));
        __half2 sz = __hadd2(__hadd2(h2(r0.z), h2(r1.z)), __hadd2(h2(r2.z), h2(r3.z)));
        __half2 sw = __hadd2(__hadd2(h2(r0.w), h2(r1.w)), __hadd2(h2(r2.w), h2(r3.w)));
        float2 fx = __half22float2(sx);
        float2 fy = __half22float2(sy);
        float2 fz = __half22float2(sz);
        float2 fw = __half22float2(sw);
        acc[0] += fx.x; acc[1] += fx.y;
        acc[2] += fy.x; acc[3] += fy.y;
        acc[4] += fz.x; acc[5] += fz.y;
        acc[6] += fw.x; acc[7] += fw.y;
    }
    for (; i + 2 <= end; i += 2) {
        int s = __ldg(&g_epair[i + g].x);
        uint4 r = __ldg(rowq(mx, s, q));
        float f[8];
        cvt8(r, f);
#pragma unroll
        for (int j = 0; j < 8; j++) acc[j] += f[j];
    }
    if (i < end && g == 0) {   // odd tail: group 0 only
        int s = __ldg(&g_epair[i].x);
        uint4 r = __ldg(rowq(mx, s, q));
        float f[8];
        cvt8(r, f);
#pragma unroll
        for (int j = 0; j < 8; j++) acc[j] += f[j];
    }

    // combine the two halves (disjoint edge sets)
#pragma unroll
    for (int j = 0; j < 8; j++) acc[j] += __shfl_xor_sync(0xFFFFFFFFu, acc[j], 16);

    if (g == 0) {
        float inv = g_inv[n];
        uint4 hv;
        __half2 h;
        h = __floats2half2_rn(acc[0] * inv, acc[1] * inv); hv.x = *reinterpret_cast<unsigned*>(&h);
        h = __floats2half2_rn(acc[2] * inv, acc[3] * inv); hv.y = *reinterpret_cast<unsigned*>(&h);
        h = __floats2half2_rn(acc[4] * inv, acc[5] * inv); hv.z = *reinterpret_cast<unsigned*>(&h);
        h = __floats2half2_rn(acc[6] * inv, acc[7] * inv); hv.w = *reinterpret_cast<unsigned*>(&h);
        ((uint4*)(g_aggh + (size_t)n * 64))[q] = hv;
    }
}

// ---------------------------------------------------------------------------
// node transform via tensor cores, persistent blocks:
//   out[n][o] = sum_k A[n][k] * Wcat[o][k] + bl[o]   (+relu), A = [agg | x]
// tile m=64 n=128 k=256; 8 warps (2m x 4n); W staged once per block.
// ---------------------------------------------------------------------------
#define AK 264
#define MT 64
#define NT ((NN + MT - 1) / MT)   // 782 tiles
#define GRID_MMA 296
#define SMEM_MMA ((MT + 128) * AK * (int)sizeof(__half))

__device__ __forceinline__ void ldsm4(uint32_t addr, uint32_t& r0, uint32_t& r1,
                                      uint32_t& r2, uint32_t& r3) {
    asm volatile("ldmatrix.sync.aligned.m8n8.x4.shared.b16 {%0,%1,%2,%3}, [%4];"
                 : "=r"(r0), "=r"(r1), "=r"(r2), "=r"(r3) : "r"(addr));
}

__device__ __forceinline__ void mma16816(float* c, const uint32_t* a,
                                         uint32_t b0, uint32_t b1) {
    asm volatile(
        "mma.sync.aligned.m16n8k16.row.col.f32.f16.f16.f32 "
        "{%0,%1,%2,%3}, {%4,%5,%6,%7}, {%8,%9}, {%0,%1,%2,%3};"
        : "+f"(c[0]), "+f"(c[1]), "+f"(c[2]), "+f"(c[3])
        : "r"(a[0]), "r"(a[1]), "r"(a[2]), "r"(a[3]), "r"(b0), "r"(b1));
}

template <bool RELU>
__global__ __launch_bounds__(256) void k_node_mma(const __half2* __restrict__ aggh,
                                                  const __half2* __restrict__ xh,
                                                  const __half* __restrict__ wcat,
                                                  const float* __restrict__ bl,
                                                  __half2* __restrict__ mout) {
    extern __shared__ __half sh[];
    __half* A_s = sh;                 // [MT][AK]
    __half* W_s = sh + MT * AK;       // [128][AK]

    int tid = threadIdx.x;
    int wid = tid >> 5, lane = tid & 31;
    int wm = wid & 1, wn = wid >> 1;   // warp m (x2), warp n (x4)

    // stage W once
    for (int i = tid; i < 128 * 32; i += 256) {
        int row = i >> 5, s = i & 31;
        *((uint4*)(W_s + (size_t)row * AK) + s) = ((const uint4*)wcat)[i];
    }

    // per-lane ldmatrix addressing (tile-invariant)
    int lrow = (lane & 7) + (((lane >> 3) & 1) << 3);
    int lkh  = (lane >> 4) << 3;
    uint32_t a_base[2];
#pragma unroll
    for (int mt = 0; mt < 2; mt++)
        a_base[mt] = (uint32_t)__cvta_generic_to_shared(
            A_s + (size_t)(wm * 32 + mt * 16 + lrow) * AK + lkh);

    int bnrow = (lane & 7) + (((lane >> 4) & 1) << 3);
    int bkh   = ((lane >> 3) & 1) << 3;
    uint32_t b_base[2];
#pragma unroll
    for (int gp = 0; gp < 2; gp++)
        b_base[gp] = (uint32_t)__cvta_generic_to_shared(
            W_s + (size_t)(wn * 32 + gp * 16 + bnrow) * AK + bkh);

    int r_in = lane >> 2;
    int cpair = (lane & 3) * 2;

    for (int t = blockIdx.x; t < NT; t += GRID_MMA) {
        int base = t * MT;
        __syncthreads();   // previous iteration's MMA reads of A_s done

        // stage A = [agg | x]
        for (int i = tid; i < MT * 32; i += 256) {
            int row = i >> 5, s = i & 31;
            int n = base + row;
            uint4 v = make_uint4(0, 0, 0, 0);
            if (n < NN)
                v = (s < 16) ? ((const uint4*)aggh)[(size_t)n * 16 + s]
                             : ((const uint4*)xh)[(size_t)n * 16 + (s - 16)];
            *((uint4*)(A_s + (size_t)row * AK) + s) = v;
        }
        __syncthreads();

        float acc[2][4][4];
#pragma unroll
        for (int mt = 0; mt < 2; mt++)
#pragma unroll
            for (int g = 0; g < 4; g++)
#pragma unroll
                for (int j = 0; j < 4; j++) acc[mt][g][j] = 0.0f;

#pragma unroll 4
        for (int kc = 0; kc < 16; kc++) {
            uint32_t koff = kc * 32;
            uint32_t a[2][4];
            ldsm4(a_base[0] + koff, a[0][0], a[0][1], a[0][2], a[0][3]);
            ldsm4(a_base[1] + koff, a[1][0], a[1][1], a[1][2], a[1][3]);
#pragma unroll
            for (int gp = 0; gp < 2; gp++) {
                uint32_t b0, b1, b2, b3;
                ldsm4(b_base[gp] + koff, b0, b1, b2, b3);
#pragma unroll
                for (int mt = 0; mt < 2; mt++) {
                    mma16816(acc[mt][gp * 2 + 0], a[mt], b0, b1);
                    mma16816(acc[mt][gp * 2 + 1], a[mt], b2, b3);
                }
            }
        }

        // epilogue: bias + relu + fp16 store
#pragma unroll
        for (int mt = 0; mt < 2; mt++) {
#pragma unroll
            for (int g = 0; g < 4; g++) {
                int col = wn * 32 + g * 8 + cpair;
                float2 b2 = *(const float2*)(bl + col);
                float x0 = acc[mt][g][0] + b2.x;
                float y0 = acc[mt][g][1] + b2.y;
                float x1 = acc[mt][g][2] + b2.x;
                float y1 = acc[mt][g][3] + b2.y;
                if (RELU) {
                    x0 = fmaxf(x0, 0.0f); y0 = fmaxf(y0, 0.0f);
                    x1 = fmaxf(x1, 0.0f); y1 = fmaxf(y1, 0.0f);
                }
                int row0 = base + wm * 32 + mt * 16 + r_in;
                int row1 = row0 + 8;
                if (row0 < NN) mout[(size_t)row0 * 64 + (col >> 1)] = __floats2half2_rn(x0, y0);
                if (row1 < NN) mout[(size_t)row1 * 64 + (col >> 1)] = __floats2half2_rn(x1, y1);
            }
        }
    }
}

// ---------------------------------------------------------------------------
// edge output via CSR: one warp per dst node, half-warp per edge (LDG.128).
// ---------------------------------------------------------------------------
__device__ __forceinline__ float half_red(float v) {
#pragma unroll
    for (int off = 8; off; off >>= 1) v += __shfl_xor_sync(0xFFFFFFFFu, v, off);
    return v;   // lanes 0 and 16 hold their group's sum
}

__device__ __forceinline__ float dot8(const float* a, const float* b) {
    return (a[0] * b[0] + a[1] * b[1]) + (a[2] * b[2] + a[3] * b[3])
         + (a[4] * b[4] + a[5] * b[5]) + (a[6] * b[6] + a[7] * b[7]);
}

__global__ __launch_bounds__(256) void k_edge_csr(const __half2* __restrict__ mx,
                                                  float* __restrict__ out) {
    int n = (blockIdx.x * blockDim.x + threadIdx.x) >> 5;
    int lane = threadIdx.x & 31;
    if (n >= NN) return;
    int q = lane & 15;
    int g = lane >> 4;
    int beg = g_off[n], end = g_off[n + 1];
    if (beg == end) return;

    float bf[8];
    {
        uint4 r = __ldg(rowq(mx, n, q));
        cvt8(r, bf);
    }

    int i = beg;
    for (; i + 8 <= end; i += 8) {
        int2 p0 = __ldg(&g_epair[i + 0 + g]);
        int2 p1 = __ldg(&g_epair[i + 2 + g]);
        int2 p2 = __ldg(&g_epair[i + 4 + g]);
        int2 p3 = __ldg(&g_epair[i + 6 + g]);
        uint4 r0 = __ldg(rowq(mx, p0.x, q));
        uint4 r1 = __ldg(rowq(mx, p1.x, q));
        uint4 r2 = __ldg(rowq(mx, p2.x, q));
        uint4 r3 = __ldg(rowq(mx, p3.x, q));
        float f[8];
        cvt8(r0, f); float v0 = half_red(dot8(f, bf));
        cvt8(r1, f); float v1 = half_red(dot8(f, bf));
        cvt8(r2, f); float v2 = half_red(dot8(f, bf));
        cvt8(r3, f); float v3 = half_red(dot8(f, bf));
        if (q == 0) {
            out[p0.y] = v0;
            out[p1.y] = v1;
            out[p2.y] = v2;
            out[p3.y] = v3;
        }
    }
    for (; i + 2 <= end; i += 2) {
        int2 p = __ldg(&g_epair[i + g]);
        uint4 r = __ldg(rowq(mx, p.x, q));
        float f[8];
        cvt8(r, f);
        float v = half_red(dot8(f, bf));
        if (q == 0) out[p.y] = v;
    }
    if (i < end) {   // odd tail: both groups compute same edge; lane 0 writes
        int2 p = __ldg(&g_epair[i]);
        uint4 r = __ldg(rowq(mx, p.x, q));
        float f[8];
        cvt8(r, f);
        float v = half_red(dot8(f, bf));
        if (lane == 0) out[p.y] = v;
    }
}

// ---------------------------------------------------------------------------
extern "C" void kernel_launch(void* const* d_in, const int* in_sizes, int n_in,
                              void* d_out, int out_size) {
    const int* nid = (const int*)d_in[0];
    const int* ei  = (const int*)d_in[1];
    const float* emb = (const float*)d_in[2];
    const float* Wl1 = (const float*)d_in[3];
    const float* bl1 = (const float*)d_in[4];
    const float* Wr1 = (const float*)d_in[5];
    const float* Wl2 = (const float*)d_in[6];
    const float* bl2 = (const float*)d_in[7];
    const float* Wr2 = (const float*)d_in[8];
    float* out = (float*)d_out;

    cudaFuncSetAttribute(k_node_mma<true>,
                         cudaFuncAttributeMaxDynamicSharedMemorySize, SMEM_MMA);
    cudaFuncSetAttribute(k_node_mma<false>,
                         cudaFuncAttributeMaxDynamicSharedMemorySize, SMEM_MMA);

    __half2 *pmx, *pmh, *pagg;
    __half *pw1, *pw2;
    cudaGetSymbolAddress((void**)&pmx, g_mx);
    cudaGetSymbolAddress((void**)&pmh, g_mh);
    cudaGetSymbolAddress((void**)&pagg, g_aggh);
    cudaGetSymbolAddress((void**)&pw1, g_w1);
    cudaGetSymbolAddress((void**)&pw2, g_w2);

    int gridI  = (NN * 64 + 255) / 256;
    int gridE  = (NE + 255) / 256;
    int gridNW = (NN * 32 + 255) / 256;   // warp-per-node

    // preprocessing: features/weights/count fused; lookback scan; CSR fill
    k_prep<<<gridI, 256>>>(emb, nid, ei + NE, Wl1, Wr1, Wl2, Wr2);
    k_scan<<<NBLK, SCAN_B>>>();
    k_fill<<<gridE, 256>>>(ei);

    // Layer 1
    k_aggr<<<gridNW, 256>>>(pmx);
    k_node_mma<true><<<GRID_MMA, 256, SMEM_MMA>>>(pagg, pmx, pw1, bl1, pmh);

    // Layer 2 (output overwrites g_mx)
    k_aggr<<<gridNW, 256>>>(pmh);
    k_node_mma<false><<<GRID_MMA, 256, SMEM_MMA>>>(pagg, pmh, pw2, bl2, pmx);

    // Edge classifier
    k_edge_csr<<<gridNW, 256>>>(pmx, out);
}